// round 4
// baseline (speedup 1.0000x reference)
#include <cuda_runtime.h>
#include <cstdint>

#define THREADS 256

// B=128, L=8194, C=32, PL=8192, S=4, D=128, N=2048, tile NT=128, 16 tiles.
//
// SMEM layout rule: every array accessed via float4 (WT, Ht, ew) is placed
// first, and every array's byte size is a multiple of 16, so all LDS.128 /
// STS.128 addresses are 16B-aligned. (Previous round trapped because A's
// 10,088-byte size pushed ew to offset ≡ 8 mod 16.)
struct __align__(16) Smem {
    float WT[128 * 132];      // 67,584 B  WT[e*132+d] = W_a[d][e]
    float Ht[128 * 128];      // 65,536 B  H tile [row(d)][chunk], XOR-swizzled float4 chunks
    float ew[2048];           //  8,192 B  energies -> softmax weights (float4-read)
    float A[26 * 97 + 2];     // 10,096 B  A[letter*97 + c*3 + k] (scalar reads; padded to 16B)
    float red[128 * 17];      //  8,704 B  reduction scratch
    float va[128];            //    512 B
    float bias[32];           //    128 B
    float rscr[32];           //    128 B
    unsigned char seqb[8208]; //  8,208 B  sequence letters as bytes (uint32-read, 4-aligned)
};

__device__ __forceinline__ float tanh_fast(float x) {
    // tanh(x) = 1 - 2/(e^{2x}+1); exact saturation at +-inf; abs err ~1e-6
    float e2 = __expf(2.0f * x);
    return 1.0f - __fdividef(2.0f, e2 + 1.0f);
}

__device__ __forceinline__ void conv_tile(Smem* s, int n0, int wid, int lane) {
    // Build H tile for columns [n0, n0+128): rows d = c*4 + sct,
    // H[d][n] = relu(bias_c + A[seq[p]][c][0] + A[seq[p+1]][c][1] + A[seq[p+2]][c][2]),
    // p = sct*2048 + n.  Lane = channel c (A loads stride 3 -> conflict-free,
    // letter uniform per warp -> broadcast).  Each lane computes 4 consecutive n
    // and stores one float4 into the swizzled tile (conflict-free STS.128).
    const int c  = lane;
    const int c3 = c * 3;
    const float bias = s->bias[c];
    float4* Ht4 = (float4*)s->Ht;
    const float* A = s->A;

    #pragma unroll 2
    for (int it = wid; it < 128; it += 8) {
        int sct = it >> 5;          // section 0..3
        int ch  = it & 31;          // 4-col chunk 0..31
        int p0  = sct * 2048 + n0 + ch * 4;   // multiple of 4
        uint32_t wa = *(const uint32_t*)&s->seqb[p0];
        uint32_t wb = *(const uint32_t*)&s->seqb[p0 + 4];
        int l0 =  wa        & 255;
        int l1 = (wa >> 8)  & 255;
        int l2 = (wa >> 16) & 255;
        int l3 = (wa >> 24) & 255;
        int l4 =  wb        & 255;
        int l5 = (wb >> 8)  & 255;

        float y0 = bias + A[l0*97 + c3] + A[l1*97 + c3 + 1] + A[l2*97 + c3 + 2];
        float y1 = bias + A[l1*97 + c3] + A[l2*97 + c3 + 1] + A[l3*97 + c3 + 2];
        float y2 = bias + A[l2*97 + c3] + A[l3*97 + c3 + 1] + A[l4*97 + c3 + 2];
        float y3 = bias + A[l3*97 + c3] + A[l4*97 + c3 + 1] + A[l5*97 + c3 + 2];

        float4 y = make_float4(fmaxf(y0, 0.0f), fmaxf(y1, 0.0f),
                               fmaxf(y2, 0.0f), fmaxf(y3, 0.0f));
        int row = (c << 2) + sct;
        Ht4[row * 32 + (ch ^ (c & 7))] = y;   // swizzle key = (row>>2)&7 = c&7
    }
}

__global__ void __launch_bounds__(THREADS, 1)
dingo_kernel(const int*   __restrict__ seq,
             const float* __restrict__ emb,
             const float* __restrict__ cw,
             const float* __restrict__ cb,
             const float* __restrict__ Wa,
             const float* __restrict__ va,
             float*       __restrict__ out)
{
    extern __shared__ unsigned char dynsmem[];
    Smem* s = (Smem*)dynsmem;

    const int t    = threadIdx.x;
    const int b    = blockIdx.x;
    const int lane = t & 31;
    const int wid  = t >> 5;
    const int tx   = t & 15;          // 16 col-groups of 8
    const int ty   = t >> 4;          // 16 row-groups of 8

    // ---------------- setup ----------------
    const int* seqg = seq + b * 8194;
    for (int i = t; i < 8208; i += THREADS)
        s->seqb[i] = (i < 8194) ? (unsigned char)seqg[i] : (unsigned char)0;

    // W_a transposed into SMEM (coalesced global read)
    for (int i = t; i < 16384; i += THREADS) {
        int d = i >> 7, e = i & 127;
        s->WT[e * 132 + d] = Wa[i];
    }
    // Fold emb into conv weights: A[letter][c][k]
    for (int i = t; i < 26 * 96; i += THREADS) {
        int letter = i / 96, r = i % 96;
        int c = r / 3, k = r % 3;
        float acc = 0.0f;
        #pragma unroll
        for (int j = 0; j < 5; j++)
            acc += emb[letter * 5 + j] * cw[c * 15 + j * 3 + k];
        s->A[letter * 97 + r] = acc;
    }
    if (t < 128) s->va[t]  = va[t];
    if (t < 32)  s->bias[t] = cb[t];
    __syncthreads();

    float vr[8];
    #pragma unroll
    for (int i = 0; i < 8; i++) vr[i] = s->va[ty * 8 + i];

    const float4* Ht4 = (const float4*)s->Ht;
    const int c0 = tx * 2, c1 = tx * 2 + 1;

    // ---------------- pass 1: energies ----------------
    for (int tile = 0; tile < 16; tile++) {
        const int n0 = tile * 128;
        conv_tile(s, n0, wid, lane);
        __syncthreads();

        float acc[8][8];
        #pragma unroll
        for (int i = 0; i < 8; i++)
            #pragma unroll
            for (int j = 0; j < 8; j++) acc[i][j] = 0.0f;

        #pragma unroll 8
        for (int k = 0; k < 128; k++) {
            float4 a0 = *(const float4*)(s->WT + k * 132 + ty * 8);
            float4 a1 = *(const float4*)(s->WT + k * 132 + ty * 8 + 4);
            int g = (k >> 2) & 7;
            float4 b0 = Ht4[k * 32 + (c0 ^ g)];
            float4 b1 = Ht4[k * 32 + (c1 ^ g)];
            float ar[8] = {a0.x, a0.y, a0.z, a0.w, a1.x, a1.y, a1.z, a1.w};
            float br[8] = {b0.x, b0.y, b0.z, b0.w, b1.x, b1.y, b1.z, b1.w};
            #pragma unroll
            for (int i = 0; i < 8; i++)
                #pragma unroll
                for (int j = 0; j < 8; j++)
                    acc[i][j] = fmaf(ar[i], br[j], acc[i][j]);
        }

        // e-partials: sum_i v[i] * tanh(acc[i][j]) per owned column
        #pragma unroll
        for (int j = 0; j < 8; j++) {
            float p = 0.0f;
            #pragma unroll
            for (int i = 0; i < 8; i++)
                p += vr[i] * tanh_fast(acc[i][j]);
            s->red[(tx * 8 + j) * 17 + ty] = p;
        }
        __syncthreads();
        if (t < 128) {
            float ssum = 0.0f;
            #pragma unroll
            for (int g2 = 0; g2 < 16; g2++) ssum += s->red[t * 17 + g2];
            s->ew[n0 + t] = ssum;
        }
        __syncthreads();
    }

    // ---------------- softmax over 2048 ----------------
    float m = -1e30f;
    #pragma unroll
    for (int i = 0; i < 8; i++) m = fmaxf(m, s->ew[t + i * 256]);
    #pragma unroll
    for (int o = 16; o; o >>= 1) m = fmaxf(m, __shfl_xor_sync(0xffffffffu, m, o));
    if (lane == 0) s->rscr[wid] = m;
    __syncthreads();
    float mm = s->rscr[0];
    #pragma unroll
    for (int w2 = 1; w2 < 8; w2++) mm = fmaxf(mm, s->rscr[w2]);
    __syncthreads();                       // protect rscr reuse

    float lsum = 0.0f;
    #pragma unroll
    for (int i = 0; i < 8; i++) {
        float v = __expf(s->ew[t + i * 256] - mm);
        s->ew[t + i * 256] = v;
        lsum += v;
    }
    #pragma unroll
    for (int o = 16; o; o >>= 1) lsum += __shfl_xor_sync(0xffffffffu, lsum, o);
    if (lane == 0) s->rscr[wid] = lsum;
    __syncthreads();
    float tot = 0.0f;
    #pragma unroll
    for (int w2 = 0; w2 < 8; w2++) tot += s->rscr[w2];
    float inv = 1.0f / tot;
    #pragma unroll
    for (int i = 0; i < 8; i++) s->ew[t + i * 256] *= inv;
    __syncthreads();

    // ---------------- pass 2: weighted pooling (recompute H) ----------------
    float cacc[8];
    #pragma unroll
    for (int i = 0; i < 8; i++) cacc[i] = 0.0f;

    for (int tile = 0; tile < 16; tile++) {
        const int n0 = tile * 128;
        conv_tile(s, n0, wid, lane);
        __syncthreads();

        float4 w0 = *(const float4*)(s->ew + n0 + tx * 8);
        float4 w1 = *(const float4*)(s->ew + n0 + tx * 8 + 4);
        #pragma unroll
        for (int i = 0; i < 8; i++) {
            int row = ty * 8 + i;
            int g = (row >> 2) & 7;
            float4 h0 = Ht4[row * 32 + (c0 ^ g)];
            float4 h1 = Ht4[row * 32 + (c1 ^ g)];
            cacc[i] += w0.x * h0.x + w0.y * h0.y + w0.z * h0.z + w0.w * h0.w
                     + w1.x * h1.x + w1.y * h1.y + w1.z * h1.z + w1.w * h1.w;
        }
        __syncthreads();
    }

    #pragma unroll
    for (int i = 0; i < 8; i++) s->red[(ty * 8 + i) * 17 + tx] = cacc[i];
    __syncthreads();
    if (t < 128) {
        float ssum = 0.0f;
        #pragma unroll
        for (int g2 = 0; g2 < 16; g2++) ssum += s->red[t * 17 + g2];
        out[b * 128 + t] = ssum;
    }
}

extern "C" void kernel_launch(void* const* d_in, const int* in_sizes, int n_in,
                              void* d_out, int out_size)
{
    const int*   seq = (const int*)  d_in[0];
    const float* emb = (const float*)d_in[1];
    const float* cw  = (const float*)d_in[2];
    const float* cb  = (const float*)d_in[3];
    const float* Wa  = (const float*)d_in[4];
    const float* va  = (const float*)d_in[5];
    float* out = (float*)d_out;

    cudaFuncSetAttribute(dingo_kernel,
                         cudaFuncAttributeMaxDynamicSharedMemorySize,
                         (int)sizeof(Smem));
    dingo_kernel<<<128, THREADS, sizeof(Smem)>>>(seq, emb, cw, cb, Wa, va, out);
}

// round 5
// speedup vs baseline: 1.0056x; 1.0056x over previous
#include <cuda_runtime.h>
#include <cstdint>

#define THREADS 256

// B=128, L=8194, C=32, PL=8192, S=4, D=128, N=2048, tile NT=128, 16 tiles.
//
// SMEM layout rule: every array accessed via 128-bit LDS/STS (WT, Ht, ew) is
// placed first and every array's byte size is a multiple of 16, so all
// LDS.128 / STS.128 addresses are 16B-aligned.
struct __align__(16) Smem {
    float WT[128 * 132];      // 67,584 B  WT[e*132+d] = W_a[d][e]
    float Ht[128 * 128];      // 65,536 B  H tile [row(d)][chunk], XOR-swizzled float4 chunks
    float ew[2048];           //  8,192 B  energies -> softmax weights (float4-read)
    float A[26 * 97 + 2];     // 10,096 B  A[letter*97 + c*3 + k] (scalar reads; padded to 16B)
    float red[128 * 17];      //  8,704 B  reduction scratch
    float va[128];            //    512 B
    float bias[32];           //    128 B
    float rscr[32];           //    128 B
    unsigned char seqb[8208]; //  8,208 B  sequence letters as bytes (uint32-read, 4-aligned)
};

// Packed f32x2 FMA: 2 MACs per issue slot. ptxas never emits FFMA2 from C++;
// PTX `fma.rn.f32x2` is the only route (see SASS_QUICKREF "patterns absent").
__device__ __forceinline__ void ffma2(unsigned long long& d,
                                      unsigned long long a,
                                      unsigned long long b) {
    asm("fma.rn.f32x2 %0, %1, %2, %0;" : "+l"(d) : "l"(a), "l"(b));
}
__device__ __forceinline__ unsigned long long dup2(float x) {
    unsigned long long r;
    asm("mov.b64 %0, {%1, %1};" : "=l"(r) : "f"(x));
    return r;
}
__device__ __forceinline__ void unpack2(unsigned long long p, float& lo, float& hi) {
    asm("mov.b64 {%0, %1}, %2;" : "=f"(lo), "=f"(hi) : "l"(p));
}

__device__ __forceinline__ float tanh_fast(float x) {
    // tanh(x) = 1 - 2/(e^{2x}+1); exact saturation at +-inf; abs err ~1e-6
    float e2 = __expf(2.0f * x);
    return 1.0f - __fdividef(2.0f, e2 + 1.0f);
}

__device__ __forceinline__ void conv_tile(Smem* s, int n0, int wid, int lane) {
    // Build H tile for columns [n0, n0+128): rows d = c*4 + sct,
    // H[d][n] = relu(bias_c + A[seq[p]][c][0] + A[seq[p+1]][c][1] + A[seq[p+2]][c][2]),
    // p = sct*2048 + n.  Lane = channel c (A loads stride 3 -> conflict-free,
    // letter uniform per warp -> broadcast).  Each lane computes 4 consecutive n
    // and stores one float4 into the swizzled tile (conflict-free STS.128).
    const int c  = lane;
    const int c3 = c * 3;
    const float bias = s->bias[c];
    float4* Ht4 = (float4*)s->Ht;
    const float* A = s->A;

    #pragma unroll 2
    for (int it = wid; it < 128; it += 8) {
        int sct = it >> 5;          // section 0..3
        int ch  = it & 31;          // 4-col chunk 0..31
        int p0  = sct * 2048 + n0 + ch * 4;   // multiple of 4
        uint32_t wa = *(const uint32_t*)&s->seqb[p0];
        uint32_t wb = *(const uint32_t*)&s->seqb[p0 + 4];
        int l0 =  wa        & 255;
        int l1 = (wa >> 8)  & 255;
        int l2 = (wa >> 16) & 255;
        int l3 = (wa >> 24) & 255;
        int l4 =  wb        & 255;
        int l5 = (wb >> 8)  & 255;

        float y0 = bias + A[l0*97 + c3] + A[l1*97 + c3 + 1] + A[l2*97 + c3 + 2];
        float y1 = bias + A[l1*97 + c3] + A[l2*97 + c3 + 1] + A[l3*97 + c3 + 2];
        float y2 = bias + A[l2*97 + c3] + A[l3*97 + c3 + 1] + A[l4*97 + c3 + 2];
        float y3 = bias + A[l3*97 + c3] + A[l4*97 + c3 + 1] + A[l5*97 + c3 + 2];

        float4 y = make_float4(fmaxf(y0, 0.0f), fmaxf(y1, 0.0f),
                               fmaxf(y2, 0.0f), fmaxf(y3, 0.0f));
        int row = (c << 2) + sct;
        Ht4[row * 32 + (ch ^ (c & 7))] = y;   // swizzle key = (row>>2)&7 = c&7
    }
}

__global__ void __launch_bounds__(THREADS, 1)
dingo_kernel(const int*   __restrict__ seq,
             const float* __restrict__ emb,
             const float* __restrict__ cw,
             const float* __restrict__ cb,
             const float* __restrict__ Wa,
             const float* __restrict__ va,
             float*       __restrict__ out)
{
    extern __shared__ unsigned char dynsmem[];
    Smem* s = (Smem*)dynsmem;

    const int t    = threadIdx.x;
    const int b    = blockIdx.x;
    const int lane = t & 31;
    const int wid  = t >> 5;
    const int tx   = t & 15;          // 16 col-groups of 8
    const int ty   = t >> 4;          // 16 row-groups of 8

    // ---------------- setup ----------------
    const int* seqg = seq + b * 8194;
    for (int i = t; i < 8208; i += THREADS)
        s->seqb[i] = (i < 8194) ? (unsigned char)seqg[i] : (unsigned char)0;

    // W_a transposed into SMEM (coalesced global read)
    for (int i = t; i < 16384; i += THREADS) {
        int d = i >> 7, e = i & 127;
        s->WT[e * 132 + d] = Wa[i];
    }
    // Fold emb into conv weights: A[letter][c][k]
    for (int i = t; i < 26 * 96; i += THREADS) {
        int letter = i / 96, r = i % 96;
        int c = r / 3, k = r % 3;
        float acc = 0.0f;
        #pragma unroll
        for (int j = 0; j < 5; j++)
            acc += emb[letter * 5 + j] * cw[c * 15 + j * 3 + k];
        s->A[letter * 97 + r] = acc;
    }
    if (t < 128) s->va[t]  = va[t];
    if (t < 32)  s->bias[t] = cb[t];
    __syncthreads();

    float vr[8];
    #pragma unroll
    for (int i = 0; i < 8; i++) vr[i] = s->va[ty * 8 + i];

    const float4*     Ht4 = (const float4*)s->Ht;
    const ulonglong2* Ht2 = (const ulonglong2*)s->Ht;   // same chunks as 2x packed f32 pairs
    const int c0 = tx * 2, c1 = tx * 2 + 1;

    // ---------------- pass 1: energies ----------------
    for (int tile = 0; tile < 16; tile++) {
        const int n0 = tile * 128;
        conv_tile(s, n0, wid, lane);
        __syncthreads();

        // acc2[i][j] packs output columns (2j, 2j+1) of this thread's 8 columns.
        unsigned long long acc2[8][4];
        #pragma unroll
        for (int i = 0; i < 8; i++)
            #pragma unroll
            for (int j = 0; j < 4; j++) acc2[i][j] = 0ULL;

        #pragma unroll 4
        for (int k = 0; k < 128; k++) {
            float4 a0 = *(const float4*)(s->WT + k * 132 + ty * 8);
            float4 a1 = *(const float4*)(s->WT + k * 132 + ty * 8 + 4);
            int g = (k >> 2) & 7;
            ulonglong2 b0 = Ht2[k * 32 + (c0 ^ g)];   // cols 8tx+0..3 (two packed pairs)
            ulonglong2 b1 = Ht2[k * 32 + (c1 ^ g)];   // cols 8tx+4..7
            unsigned long long bb[4] = {b0.x, b0.y, b1.x, b1.y};
            unsigned long long ad[8];
            ad[0] = dup2(a0.x); ad[1] = dup2(a0.y);
            ad[2] = dup2(a0.z); ad[3] = dup2(a0.w);
            ad[4] = dup2(a1.x); ad[5] = dup2(a1.y);
            ad[6] = dup2(a1.z); ad[7] = dup2(a1.w);
            #pragma unroll
            for (int i = 0; i < 8; i++)
                #pragma unroll
                for (int j = 0; j < 4; j++)
                    ffma2(acc2[i][j], ad[i], bb[j]);
        }

        // e-partials: p[j] = sum_i v[i] * tanh(acc[i][j]) per owned column
        #pragma unroll
        for (int jp = 0; jp < 4; jp++) {
            float plo = 0.0f, phi = 0.0f;
            #pragma unroll
            for (int i = 0; i < 8; i++) {
                float lo, hi;
                unpack2(acc2[i][jp], lo, hi);
                plo += vr[i] * tanh_fast(lo);
                phi += vr[i] * tanh_fast(hi);
            }
            s->red[(tx * 8 + jp * 2    ) * 17 + ty] = plo;
            s->red[(tx * 8 + jp * 2 + 1) * 17 + ty] = phi;
        }
        __syncthreads();
        if (t < 128) {
            float ssum = 0.0f;
            #pragma unroll
            for (int g2 = 0; g2 < 16; g2++) ssum += s->red[t * 17 + g2];
            s->ew[n0 + t] = ssum;
        }
        __syncthreads();
    }

    // ---------------- softmax over 2048 ----------------
    float m = -1e30f;
    #pragma unroll
    for (int i = 0; i < 8; i++) m = fmaxf(m, s->ew[t + i * 256]);
    #pragma unroll
    for (int o = 16; o; o >>= 1) m = fmaxf(m, __shfl_xor_sync(0xffffffffu, m, o));
    if (lane == 0) s->rscr[wid] = m;
    __syncthreads();
    float mm = s->rscr[0];
    #pragma unroll
    for (int w2 = 1; w2 < 8; w2++) mm = fmaxf(mm, s->rscr[w2]);
    __syncthreads();                       // protect rscr reuse

    float lsum = 0.0f;
    #pragma unroll
    for (int i = 0; i < 8; i++) {
        float v = __expf(s->ew[t + i * 256] - mm);
        s->ew[t + i * 256] = v;
        lsum += v;
    }
    #pragma unroll
    for (int o = 16; o; o >>= 1) lsum += __shfl_xor_sync(0xffffffffu, lsum, o);
    if (lane == 0) s->rscr[wid] = lsum;
    __syncthreads();
    float tot = 0.0f;
    #pragma unroll
    for (int w2 = 0; w2 < 8; w2++) tot += s->rscr[w2];
    float inv = 1.0f / tot;
    #pragma unroll
    for (int i = 0; i < 8; i++) s->ew[t + i * 256] *= inv;
    __syncthreads();

    // ---------------- pass 2: weighted pooling (recompute H) ----------------
    float cacc[8];
    #pragma unroll
    for (int i = 0; i < 8; i++) cacc[i] = 0.0f;

    for (int tile = 0; tile < 16; tile++) {
        const int n0 = tile * 128;
        conv_tile(s, n0, wid, lane);
        __syncthreads();

        float4 w0 = *(const float4*)(s->ew + n0 + tx * 8);
        float4 w1 = *(const float4*)(s->ew + n0 + tx * 8 + 4);
        #pragma unroll
        for (int i = 0; i < 8; i++) {
            int row = ty * 8 + i;
            int g = (row >> 2) & 7;
            float4 h0 = Ht4[row * 32 + (c0 ^ g)];
            float4 h1 = Ht4[row * 32 + (c1 ^ g)];
            cacc[i] += w0.x * h0.x + w0.y * h0.y + w0.z * h0.z + w0.w * h0.w
                     + w1.x * h1.x + w1.y * h1.y + w1.z * h1.z + w1.w * h1.w;
        }
        __syncthreads();
    }

    #pragma unroll
    for (int i = 0; i < 8; i++) s->red[(ty * 8 + i) * 17 + tx] = cacc[i];
    __syncthreads();
    if (t < 128) {
        float ssum = 0.0f;
        #pragma unroll
        for (int g2 = 0; g2 < 16; g2++) ssum += s->red[t * 17 + g2];
        out[b * 128 + t] = ssum;
    }
}

extern "C" void kernel_launch(void* const* d_in, const int* in_sizes, int n_in,
                              void* d_out, int out_size)
{
    const int*   seq = (const int*)  d_in[0];
    const float* emb = (const float*)d_in[1];
    const float* cw  = (const float*)d_in[2];
    const float* cb  = (const float*)d_in[3];
    const float* Wa  = (const float*)d_in[4];
    const float* va  = (const float*)d_in[5];
    float* out = (float*)d_out;

    cudaFuncSetAttribute(dingo_kernel,
                         cudaFuncAttributeMaxDynamicSharedMemorySize,
                         (int)sizeof(Smem));
    dingo_kernel<<<128, THREADS, sizeof(Smem)>>>(seq, emb, cw, cb, Wa, va, out);
}

// round 7
// speedup vs baseline: 1.9612x; 1.9503x over previous
#include <cuda_runtime.h>
#include <cstdint>

#define THREADS 512

// B=128, L=8194, C=32, PL=8192, S=4, D=128(M=K), N=2048, 16 n-tiles of 128.
// T = W_a @ H per n-tile via mma.sync.m16n8k16 bf16 split-2:
//   T ~= Whi*Hhi + Whi*Hlo + Wlo*Hhi      (lo*lo dropped, ~2^-16 rel)
// Tiles stored [row][k] bf16 with 272B pitch (272 = 16 mod 128 -> every row
// starts 4 banks later; all fragment LDS.32 patterns are conflict-free).

#define OFF_AHI  0          // bf16 Whi [128][136]  34,816 B
#define OFF_ALO  34816      // bf16 Wlo            34,816 B
#define OFF_B    69632      // pass1: bf16 Hhi tile [n][k]; pass2: f32 H [n][136]
#define OFF_BLO  104448     // pass1: bf16 Hlo tile
#define OFF_EW   139264     // float[2048]
#define OFF_AT   147456     // float AT[26][3][32]  9,984 B (conv table, c fastest)
#define OFF_RED  157440     // 4,096 B reduction scratch
#define OFF_VA   161536     // float[128]
#define OFF_BIAS 162048     // float[32]
#define OFF_RSCR 162176     // float[16]
#define OFF_SEQ  162240     // uchar[8208]
#define SMEM_TOTAL 170448

// pack: low16 = bf16(lo), high16 = bf16(hi)
__device__ __forceinline__ uint32_t pack_bf(float lo, float hi) {
    uint32_t r;
    asm("cvt.rn.bf16x2.f32 %0, %1, %2;" : "=r"(r) : "f"(hi), "f"(lo));
    return r;
}
__device__ __forceinline__ float tanh_fast(float x) {
    // tanh(x) = 1 - 2/(e^{2x}+1); exact saturation; abs err ~1e-6
    float e2 = __expf(2.0f * x);
    return 1.0f - __fdividef(2.0f, e2 + 1.0f);
}
__device__ __forceinline__ void mma_bf16(float* d, const uint32_t* a, const uint32_t* b) {
    asm("mma.sync.aligned.m16n8k16.row.col.f32.bf16.bf16.f32 "
        "{%0,%1,%2,%3}, {%4,%5,%6,%7}, {%8,%9}, {%0,%1,%2,%3};"
        : "+f"(d[0]), "+f"(d[1]), "+f"(d[2]), "+f"(d[3])
        : "r"(a[0]), "r"(a[1]), "r"(a[2]), "r"(a[3]), "r"(b[0]), "r"(b[1]));
}

// Conv values for unit u (sct pair sp = u>>5, 4-col chunk ch = u&31), channel
// c = lane.  Letters are warp-uniform (all lanes share u); table loads
// AT[l][k][c] are lane-coalesced -> 1 wavefront each.
__device__ __forceinline__ void conv_vals(const char* sm, int n0, int u, int c,
                                          float bias, float* ya, float* yb) {
    const unsigned char* seqb = (const unsigned char*)(sm + OFF_SEQ);
    const float* AT = (const float*)(sm + OFF_AT);
    int sp = u >> 5, ch = u & 31;
    int na = ch * 4;
    int p0 = sp * 4096 + n0 + na;   // sct = 2sp
    int p1 = p0 + 2048;             // sct = 2sp+1
    uint32_t wa0 = *(const uint32_t*)(seqb + p0);
    uint32_t wb0 = *(const uint32_t*)(seqb + p0 + 4);
    uint32_t wa1 = *(const uint32_t*)(seqb + p1);
    uint32_t wb1 = *(const uint32_t*)(seqb + p1 + 4);
#define TBL(l, k) AT[(((l) * 3 + (k)) << 5) + c]
    {
        int l0 = wa0 & 255, l1 = (wa0 >> 8) & 255, l2 = (wa0 >> 16) & 255, l3 = wa0 >> 24;
        int l4 = wb0 & 255, l5 = (wb0 >> 8) & 255;
        float t00 = TBL(l0,0), t10 = TBL(l1,0), t11 = TBL(l1,1), t20 = TBL(l2,0);
        float t21 = TBL(l2,1), t22 = TBL(l2,2), t30 = TBL(l3,0), t31 = TBL(l3,1);
        float t32 = TBL(l3,2), t41 = TBL(l4,1), t42 = TBL(l4,2), t52 = TBL(l5,2);
        ya[0] = fmaxf(bias + t00 + t11 + t22, 0.0f);
        ya[1] = fmaxf(bias + t10 + t21 + t32, 0.0f);
        ya[2] = fmaxf(bias + t20 + t31 + t42, 0.0f);
        ya[3] = fmaxf(bias + t30 + t41 + t52, 0.0f);
    }
    {
        int l0 = wa1 & 255, l1 = (wa1 >> 8) & 255, l2 = (wa1 >> 16) & 255, l3 = wa1 >> 24;
        int l4 = wb1 & 255, l5 = (wb1 >> 8) & 255;
        float t00 = TBL(l0,0), t10 = TBL(l1,0), t11 = TBL(l1,1), t20 = TBL(l2,0);
        float t21 = TBL(l2,1), t22 = TBL(l2,2), t30 = TBL(l3,0), t31 = TBL(l3,1);
        float t32 = TBL(l3,2), t41 = TBL(l4,1), t42 = TBL(l4,2), t52 = TBL(l5,2);
        yb[0] = fmaxf(bias + t00 + t11 + t22, 0.0f);
        yb[1] = fmaxf(bias + t10 + t21 + t32, 0.0f);
        yb[2] = fmaxf(bias + t20 + t31 + t42, 0.0f);
        yb[3] = fmaxf(bias + t30 + t41 + t52, 0.0f);
    }
#undef TBL
}

// Pass-1 producer: bf16 hi/lo H^T tile [n][k=e], pitch 272B.
// ya -> e row 4c+2sp, yb -> 4c+2sp+1 (adjacent) => one 32-bit store each.
__device__ __forceinline__ void conv_bf16(char* sm, int n0, int wid, int lane) {
    const int c = lane;
    const float bias = ((const float*)(sm + OFF_BIAS))[c];
    for (int u = wid; u < 64; u += 16) {
        float ya[4], yb[4];
        conv_vals(sm, n0, u, c, bias, ya, yb);
        int sp = u >> 5, na = (u & 31) * 4;
        int e0 = 4 * c + 2 * sp;
        #pragma unroll
        for (int j = 0; j < 4; j++) {
            int row = na + j;
            uint32_t hw = pack_bf(ya[j], yb[j]);
            float ha = __uint_as_float(hw << 16);
            float hb = __uint_as_float(hw & 0xFFFF0000u);
            uint32_t lw = pack_bf(ya[j] - ha, yb[j] - hb);
            *(uint32_t*)(sm + OFF_B   + row * 272 + e0 * 2) = hw;
            *(uint32_t*)(sm + OFF_BLO + row * 272 + e0 * 2) = lw;
        }
    }
}

// Pass-2 producer: exact fp32 H^T tile [n][e], pitch 544B (float2 pairs).
__device__ __forceinline__ void conv_f32(char* sm, int n0, int wid, int lane) {
    const int c = lane;
    const float bias = ((const float*)(sm + OFF_BIAS))[c];
    for (int u = wid; u < 64; u += 16) {
        float ya[4], yb[4];
        conv_vals(sm, n0, u, c, bias, ya, yb);
        int sp = u >> 5, na = (u & 31) * 4;
        int e0 = 4 * c + 2 * sp;
        #pragma unroll
        for (int j = 0; j < 4; j++)
            *(float2*)(sm + OFF_B + (na + j) * 544 + e0 * 4) = make_float2(ya[j], yb[j]);
    }
}

__global__ void __launch_bounds__(THREADS, 1)
dingo_mma_kernel(const int*   __restrict__ seq,
                 const float* __restrict__ emb,
                 const float* __restrict__ cw,
                 const float* __restrict__ cb,
                 const float* __restrict__ Wa,
                 const float* __restrict__ va,
                 float*       __restrict__ out)
{
    extern __shared__ char sm[];
    const int t    = threadIdx.x;
    const int b    = blockIdx.x;
    const int lane = t & 31;
    const int wid  = t >> 5;              // 0..15

    // ---------------- setup ----------------
    const int* seqg = seq + b * 8194;
    unsigned char* seqb = (unsigned char*)(sm + OFF_SEQ);
    for (int i = t; i < 8208; i += THREADS)
        seqb[i] = (i < 8194) ? (unsigned char)seqg[i] : (unsigned char)0;

    // W_a -> bf16 hi/lo [m][k] pitch 272B
    for (int i = t; i < 16384; i += THREADS) {
        int d = i >> 7, e = i & 127;      // Wa[d][e]
        float w = Wa[i];
        uint32_t hp = pack_bf(w, 0.0f);
        float hf = __uint_as_float(hp << 16);
        uint32_t lp = pack_bf(w - hf, 0.0f);
        *(unsigned short*)(sm + OFF_AHI + d * 272 + e * 2) = (unsigned short)hp;
        *(unsigned short*)(sm + OFF_ALO + d * 272 + e * 2) = (unsigned short)lp;
    }
    // Conv table AT[l][k][c] = sum_j emb[l][j] * cw[c][j][k]
    {
        float* AT = (float*)(sm + OFF_AT);
        for (int i = t; i < 26 * 96; i += THREADS) {
            int l = i / 96, r = i % 96, k = r >> 5, c = r & 31;
            float acc = 0.0f;
            #pragma unroll
            for (int j = 0; j < 5; j++)
                acc += emb[l * 5 + j] * cw[c * 15 + j * 3 + k];
            AT[i] = acc;
        }
    }
    if (t < 128) ((float*)(sm + OFF_VA))[t]   = va[t];
    if (t < 32)  ((float*)(sm + OFF_BIAS))[t] = cb[t];
    __syncthreads();

    const int warp_m = wid & 3;           // rows 32*warp_m .. +31
    const int warp_n = wid >> 2;          // cols 32*warp_n .. +31
    const int rq = lane >> 2;             // fragment row-in-group 0..7
    const int q4 = (lane & 3) * 4;        // k-pair byte offset
    const uint32_t abase = (uint32_t)((warp_m * 32 + rq) * 272 + q4);
    const uint32_t bbase = (uint32_t)((warp_n * 32 + rq) * 272 + q4);

    float vr[4];
    {
        const float* v = (const float*)(sm + OFF_VA);
        vr[0] = v[warp_m * 32 + rq];      vr[1] = v[warp_m * 32 + rq + 8];
        vr[2] = v[warp_m * 32 + rq + 16]; vr[3] = v[warp_m * 32 + rq + 24];
    }
    float* ew   = (float*)(sm + OFF_EW);
    float* red  = (float*)(sm + OFF_RED);
    float* rscr = (float*)(sm + OFF_RSCR);

    // ---------------- pass 1: energies ----------------
    for (int tile = 0; tile < 16; tile++) {
        conv_bf16(sm, tile * 128, wid, lane);
        __syncthreads();

        float acc[2][4][4];
        #pragma unroll
        for (int mf = 0; mf < 2; mf++)
            #pragma unroll
            for (int nf = 0; nf < 4; nf++)
                #pragma unroll
                for (int r = 0; r < 4; r++) acc[mf][nf][r] = 0.0f;

        #pragma unroll
        for (int ks = 0; ks < 8; ks++) {
            const uint32_t kb = (uint32_t)ks * 32;
            uint32_t ah[2][4], al[2][4], bh[4][2], bl[4][2];
            #pragma unroll
            for (int mf = 0; mf < 2; mf++) {
                uint32_t o = abase + (uint32_t)mf * 4352 + kb;
                ah[mf][0] = *(const uint32_t*)(sm + OFF_AHI + o);
                ah[mf][1] = *(const uint32_t*)(sm + OFF_AHI + o + 2176);
                ah[mf][2] = *(const uint32_t*)(sm + OFF_AHI + o + 16);
                ah[mf][3] = *(const uint32_t*)(sm + OFF_AHI + o + 2192);
                al[mf][0] = *(const uint32_t*)(sm + OFF_ALO + o);
                al[mf][1] = *(const uint32_t*)(sm + OFF_ALO + o + 2176);
                al[mf][2] = *(const uint32_t*)(sm + OFF_ALO + o + 16);
                al[mf][3] = *(const uint32_t*)(sm + OFF_ALO + o + 2192);
            }
            #pragma unroll
            for (int nf = 0; nf < 4; nf++) {
                uint32_t o = bbase + (uint32_t)nf * 2176 + kb;
                bh[nf][0] = *(const uint32_t*)(sm + OFF_B   + o);
                bh[nf][1] = *(const uint32_t*)(sm + OFF_B   + o + 16);
                bl[nf][0] = *(const uint32_t*)(sm + OFF_BLO + o);
                bl[nf][1] = *(const uint32_t*)(sm + OFF_BLO + o + 16);
            }
            #pragma unroll
            for (int mf = 0; mf < 2; mf++)
                #pragma unroll
                for (int nf = 0; nf < 4; nf++) {
                    mma_bf16(acc[mf][nf], ah[mf], bh[nf]);
                    mma_bf16(acc[mf][nf], ah[mf], bl[nf]);
                    mma_bf16(acc[mf][nf], al[mf], bh[nf]);
                }
        }

        // epilogue: p[nf*2+cc] = sum over this warp's 32 rows of v*tanh(T)
        float p[8];
        #pragma unroll
        for (int nf = 0; nf < 4; nf++)
            #pragma unroll
            for (int cc = 0; cc < 2; cc++)
                p[nf * 2 + cc] = vr[0] * tanh_fast(acc[0][nf][cc])
                               + vr[1] * tanh_fast(acc[0][nf][2 + cc])
                               + vr[2] * tanh_fast(acc[1][nf][cc])
                               + vr[3] * tanh_fast(acc[1][nf][2 + cc]);
        #pragma unroll
        for (int st = 4; st <= 16; st <<= 1)
            #pragma unroll
            for (int idx = 0; idx < 8; idx++)
                p[idx] += __shfl_xor_sync(0xffffffffu, p[idx], st);
        if (rq == 0) {   // lanes 0..3 hold full column sums
            #pragma unroll
            for (int nf = 0; nf < 4; nf++)
                #pragma unroll
                for (int cc = 0; cc < 2; cc++) {
                    int col = warp_n * 32 + nf * 8 + lane * 2 + cc;
                    red[col * 5 + warp_m] = p[nf * 2 + cc];
                }
        }
        __syncthreads();
        if (t < 128)
            ew[tile * 128 + t] = red[t * 5] + red[t * 5 + 1]
                               + red[t * 5 + 2] + red[t * 5 + 3];
        // ew-write / red-read race with next conv is fenced by next tile's sync
    }
    __syncthreads();

    // ---------------- softmax over 2048 ----------------
    {
        float m = fmaxf(fmaxf(ew[t], ew[t + 512]), fmaxf(ew[t + 1024], ew[t + 1536]));
        #pragma unroll
        for (int o = 16; o; o >>= 1) m = fmaxf(m, __shfl_xor_sync(0xffffffffu, m, o));
        if (lane == 0) rscr[wid] = m;
        __syncthreads();
        float mm = rscr[0];
        #pragma unroll
        for (int w2 = 1; w2 < 16; w2++) mm = fmaxf(mm, rscr[w2]);
        __syncthreads();
        float lsum = 0.0f;
        #pragma unroll
        for (int i = 0; i < 4; i++) {
            float v = __expf(ew[t + i * 512] - mm);
            ew[t + i * 512] = v;
            lsum += v;
        }
        #pragma unroll
        for (int o = 16; o; o >>= 1) lsum += __shfl_xor_sync(0xffffffffu, lsum, o);
        if (lane == 0) rscr[wid] = lsum;
        __syncthreads();
        float tot = 0.0f;
        #pragma unroll
        for (int w2 = 0; w2 < 16; w2++) tot += rscr[w2];
        float inv = 1.0f / tot;
        #pragma unroll
        for (int i = 0; i < 4; i++) ew[t + i * 512] *= inv;
        __syncthreads();
    }

    // ---------------- pass 2: weighted pooling (exact fp32 recompute) -------
    const int e2 = t & 63;                // output pair (2e2, 2e2+1)
    const int ng = t >> 6;                // 16 n's per subgroup
    float2 acc2 = make_float2(0.f, 0.f);

    for (int tile = 0; tile < 16; tile++) {
        conv_f32(sm, tile * 128, wid, lane);
        __syncthreads();
        const float* ww = ew + tile * 128;
        #pragma unroll 4
        for (int i = 0; i < 16; i++) {
            int n = ng * 16 + i;
            float2 h = *(const float2*)(sm + OFF_B + n * 544 + e2 * 8);
            float w = ww[n];
            acc2.x = fmaf(w, h.x, acc2.x);
            acc2.y = fmaf(w, h.y, acc2.y);
        }
        __syncthreads();
    }
    ((float2*)(sm + OFF_RED))[e2 * 8 + ng] = acc2;
    __syncthreads();
    if (t < 64) {
        float2 c2 = make_float2(0.f, 0.f);
        #pragma unroll
        for (int j = 0; j < 8; j++) {
            float2 v = ((const float2*)(sm + OFF_RED))[t * 8 + j];
            c2.x += v.x; c2.y += v.y;
        }
        out[b * 128 + 2 * t]     = c2.x;
        out[b * 128 + 2 * t + 1] = c2.y;
    }
}

extern "C" void kernel_launch(void* const* d_in, const int* in_sizes, int n_in,
                              void* d_out, int out_size)
{
    const int*   seq = (const int*)  d_in[0];
    const float* emb = (const float*)d_in[1];
    const float* cw  = (const float*)d_in[2];
    const float* cb  = (const float*)d_in[3];
    const float* Wa  = (const float*)d_in[4];
    const float* va  = (const float*)d_in[5];
    float* out = (float*)d_out;

    cudaFuncSetAttribute(dingo_mma_kernel,
                         cudaFuncAttributeMaxDynamicSharedMemorySize, SMEM_TOTAL);
    dingo_mma_kernel<<<128, THREADS, SMEM_TOTAL>>>(seq, emb, cw, cb, Wa, va, out);
}

// round 12
// speedup vs baseline: 2.2600x; 1.1523x over previous
#include <cuda_runtime.h>
#include <cstdint>
#include <math.h>

#define THREADS 512

// B=128, L=8194, C=32, PL=8192, S=4, D=128(M=K), N=2048, 16 n-tiles of 128.
// T = W_a @ H per n-tile via mma.sync.m16n8k16 bf16 split-2:
//   T ~= Whi*Hhi + Whi*Hlo + Wlo*Hhi      (lo*lo dropped, ~2^-16 rel)
// Pooling fused into pass 1 with online softmax: per tile, rescale running
// (ctx, Z) by exp(m_old - m_new) and accumulate exp(e-m)*H from the bf16
// hi/lo tile still in SMEM (H = hi + lo, 2^-16 reconstruction).
// Tiles stored [row][k] bf16, pitch 272B (272 = 16 mod 128): scalar frag
// loads AND ldmatrix row sets are bank-conflict-free.

#define OFF_AHI  0          // bf16 Whi [128][136]  34,816 B
#define OFF_ALO  34816      // bf16 Wlo             34,816 B
#define OFF_B    69632      // bf16 Hhi tile [n][k] 34,816 B
#define OFF_BLO  104448     // bf16 Hlo tile        34,816 B
#define OFF_AT   139264     // float AT[26][3][32]   9,984 B (conv table)
#define OFF_RED  149248     // 4,096 B reduction scratch (epi cols / final ctx)
#define OFF_PW   153344     // float[128] per-tile softmax numerators
#define OFF_VA   153856     // float[128]
#define OFF_BIAS 154368     // float[32]
#define OFF_RSCR 154496     // float[16]
#define OFF_SEQ  154560     // uchar[8208]
#define SMEM_TOTAL 162768

// pack: low16 = bf16(lo), high16 = bf16(hi)
__device__ __forceinline__ uint32_t pack_bf(float lo, float hi) {
    uint32_t r;
    asm("cvt.rn.bf16x2.f32 %0, %1, %2;" : "=r"(r) : "f"(hi), "f"(lo));
    return r;
}
__device__ __forceinline__ float tanh_fast(float x) {
    float e2 = __expf(2.0f * x);
    return 1.0f - __fdividef(2.0f, e2 + 1.0f);
}
__device__ __forceinline__ void mma_bf16(float* d, const uint32_t* a, const uint32_t* b) {
    asm("mma.sync.aligned.m16n8k16.row.col.f32.bf16.bf16.f32 "
        "{%0,%1,%2,%3}, {%4,%5,%6,%7}, {%8,%9}, {%0,%1,%2,%3};"
        : "+f"(d[0]), "+f"(d[1]), "+f"(d[2]), "+f"(d[3])
        : "r"(a[0]), "r"(a[1]), "r"(a[2]), "r"(a[3]), "r"(b[0]), "r"(b[1]));
}
__device__ __forceinline__ void ldsm_x4(uint32_t* r, uint32_t addr) {
    asm volatile("ldmatrix.sync.aligned.m8n8.x4.shared.b16 {%0,%1,%2,%3}, [%4];"
        : "=r"(r[0]), "=r"(r[1]), "=r"(r[2]), "=r"(r[3]) : "r"(addr));
}
__device__ __forceinline__ void ldsm_x2(uint32_t* r, uint32_t addr) {
    asm volatile("ldmatrix.sync.aligned.m8n8.x2.shared.b16 {%0,%1}, [%2];"
        : "=r"(r[0]), "=r"(r[1]) : "r"(addr));
}
__device__ __forceinline__ uint32_t smem_u32(const void* p) {
    uint32_t a;
    asm("{ .reg .u64 t; cvta.to.shared.u64 t, %1; cvt.u32.u64 %0, t; }" : "=r"(a) : "l"(p));
    return a;
}

// Conv values for unit u (sct pair sp=u>>5, chunk ch=u&31), channel c=lane.
// Letters warp-uniform; AT[l][k][c] loads lane-coalesced (1 wavefront each).
__device__ __forceinline__ void conv_vals(const char* sm, int n0, int u, int c,
                                          float bias, float* ya, float* yb) {
    const unsigned char* seqb = (const unsigned char*)(sm + OFF_SEQ);
    const float* AT = (const float*)(sm + OFF_AT);
    int sp = u >> 5, ch = u & 31;
    int na = ch * 4;
    int p0 = sp * 4096 + n0 + na;
    int p1 = p0 + 2048;
    uint32_t wa0 = *(const uint32_t*)(seqb + p0);
    uint32_t wb0 = *(const uint32_t*)(seqb + p0 + 4);
    uint32_t wa1 = *(const uint32_t*)(seqb + p1);
    uint32_t wb1 = *(const uint32_t*)(seqb + p1 + 4);
#define TBL(l, k) AT[(((l) * 3 + (k)) << 5) + c]
    {
        int l0 = wa0 & 255, l1 = (wa0 >> 8) & 255, l2 = (wa0 >> 16) & 255, l3 = wa0 >> 24;
        int l4 = wb0 & 255, l5 = (wb0 >> 8) & 255;
        float t00 = TBL(l0,0), t10 = TBL(l1,0), t11 = TBL(l1,1), t20 = TBL(l2,0);
        float t21 = TBL(l2,1), t22 = TBL(l2,2), t30 = TBL(l3,0), t31 = TBL(l3,1);
        float t32 = TBL(l3,2), t41 = TBL(l4,1), t42 = TBL(l4,2), t52 = TBL(l5,2);
        ya[0] = fmaxf(bias + t00 + t11 + t22, 0.0f);
        ya[1] = fmaxf(bias + t10 + t21 + t32, 0.0f);
        ya[2] = fmaxf(bias + t20 + t31 + t42, 0.0f);
        ya[3] = fmaxf(bias + t30 + t41 + t52, 0.0f);
    }
    {
        int l0 = wa1 & 255, l1 = (wa1 >> 8) & 255, l2 = (wa1 >> 16) & 255, l3 = wa1 >> 24;
        int l4 = wb1 & 255, l5 = (wb1 >> 8) & 255;
        float t00 = TBL(l0,0), t10 = TBL(l1,0), t11 = TBL(l1,1), t20 = TBL(l2,0);
        float t21 = TBL(l2,1), t22 = TBL(l2,2), t30 = TBL(l3,0), t31 = TBL(l3,1);
        float t32 = TBL(l3,2), t41 = TBL(l4,1), t42 = TBL(l4,2), t52 = TBL(l5,2);
        yb[0] = fmaxf(bias + t00 + t11 + t22, 0.0f);
        yb[1] = fmaxf(bias + t10 + t21 + t32, 0.0f);
        yb[2] = fmaxf(bias + t20 + t31 + t42, 0.0f);
        yb[3] = fmaxf(bias + t30 + t41 + t52, 0.0f);
    }
#undef TBL
}

// Producer: bf16 hi/lo H^T tile [n][k=e], pitch 272B.
__device__ __forceinline__ void conv_bf16(char* sm, int n0, int wid, int lane) {
    const int c = lane;
    const float bias = ((const float*)(sm + OFF_BIAS))[c];
    for (int u = wid; u < 64; u += 16) {
        float ya[4], yb[4];
        conv_vals(sm, n0, u, c, bias, ya, yb);
        int sp = u >> 5, na = (u & 31) * 4;
        int e0 = 4 * c + 2 * sp;
        #pragma unroll
        for (int j = 0; j < 4; j++) {
            int row = na + j;
            uint32_t hw = pack_bf(ya[j], yb[j]);
            float ha = __uint_as_float(hw << 16);
            float hb = __uint_as_float(hw & 0xFFFF0000u);
            uint32_t lw = pack_bf(ya[j] - ha, yb[j] - hb);
            *(uint32_t*)(sm + OFF_B   + row * 272 + e0 * 2) = hw;
            *(uint32_t*)(sm + OFF_BLO + row * 272 + e0 * 2) = lw;
        }
    }
}

__global__ void __launch_bounds__(THREADS, 1)
dingo_mma_kernel(const int*   __restrict__ seq,
                 const float* __restrict__ emb,
                 const float* __restrict__ cw,
                 const float* __restrict__ cb,
                 const float* __restrict__ Wa,
                 const float* __restrict__ va,
                 float*       __restrict__ out)
{
    extern __shared__ char sm[];
    const int t    = threadIdx.x;
    const int b    = blockIdx.x;
    const int lane = t & 31;
    const int wid  = t >> 5;              // 0..15
    const uint32_t smb = smem_u32(sm);

    // ---------------- setup ----------------
    const int* seqg = seq + b * 8194;
    unsigned char* seqb = (unsigned char*)(sm + OFF_SEQ);
    for (int i = t; i < 8208; i += THREADS)
        seqb[i] = (i < 8194) ? (unsigned char)seqg[i] : (unsigned char)0;

    for (int i = t; i < 16384; i += THREADS) {      // W_a -> bf16 hi/lo [m][k]
        int d = i >> 7, e = i & 127;
        float w = Wa[i];
        uint32_t hp = pack_bf(w, 0.0f);
        float hf = __uint_as_float(hp << 16);
        uint32_t lp = pack_bf(w - hf, 0.0f);
        *(unsigned short*)(sm + OFF_AHI + d * 272 + e * 2) = (unsigned short)hp;
        *(unsigned short*)(sm + OFF_ALO + d * 272 + e * 2) = (unsigned short)lp;
    }
    {
        float* AT = (float*)(sm + OFF_AT);           // AT[l][k][c]
        for (int i = t; i < 26 * 96; i += THREADS) {
            int l = i / 96, r = i % 96, k = r >> 5, c = r & 31;
            float acc = 0.0f;
            #pragma unroll
            for (int j = 0; j < 5; j++)
                acc += emb[l * 5 + j] * cw[c * 15 + j * 3 + k];
            AT[i] = acc;
        }
    }
    if (t < 128) ((float*)(sm + OFF_VA))[t]   = va[t];
    if (t < 32)  ((float*)(sm + OFF_BIAS))[t] = cb[t];
    __syncthreads();

    const int warp_m = wid & 3;
    const int warp_n = wid >> 2;
    // ldmatrix addresses (row sets conflict-free at pitch 272)
    const uint32_t a_off  = (uint32_t)((warp_m * 32 + (lane & 15)) * 272 + (lane >> 4) * 16);
    const uint32_t ahiA   = smb + OFF_AHI + a_off;
    const uint32_t aloA   = smb + OFF_ALO + a_off;
    const int l15 = lane & 15;
    const uint32_t b_off  = (uint32_t)((warp_n * 32 + (l15 & 7)) * 272 + (l15 >> 3) * 16);
    const uint32_t bhiA   = smb + OFF_B   + b_off;
    const uint32_t bloA   = smb + OFF_BLO + b_off;

    const int rq = lane >> 2;
    float vr[4];
    {
        const float* v = (const float*)(sm + OFF_VA);
        vr[0] = v[warp_m * 32 + rq];      vr[1] = v[warp_m * 32 + rq + 8];
        vr[2] = v[warp_m * 32 + rq + 16]; vr[3] = v[warp_m * 32 + rq + 24];
    }
    float* red  = (float*)(sm + OFF_RED);
    float* rscr = (float*)(sm + OFF_RSCR);
    float* pw   = (float*)(sm + OFF_PW);

    // online-softmax state
    const int e2 = t & 63;                // ctx e-pair (2e2, 2e2+1)
    const int ng = t >> 6;                // ctx n-subgroup (16 n's)
    float  m_run = -INFINITY;
    float  Zp = 0.0f;
    float2 ctx = make_float2(0.0f, 0.0f);

    // ---------------- single fused pass over 16 tiles ----------------
    for (int tile = 0; tile < 16; tile++) {
        conv_bf16(sm, tile * 128, wid, lane);
        __syncthreads();                               // B tile ready

        float acc[2][4][4];
        #pragma unroll
        for (int mf = 0; mf < 2; mf++)
            #pragma unroll
            for (int nf = 0; nf < 4; nf++)
                #pragma unroll
                for (int r = 0; r < 4; r++) acc[mf][nf][r] = 0.0f;

        #pragma unroll
        for (int ks = 0; ks < 8; ks++) {
            const uint32_t kb = (uint32_t)ks * 32;
            uint32_t ah[2][4], al[2][4], bh[4][2], bl[4][2];
            ldsm_x4(ah[0], ahiA + kb);
            ldsm_x4(ah[1], ahiA + 4352 + kb);
            ldsm_x4(al[0], aloA + kb);
            ldsm_x4(al[1], aloA + 4352 + kb);
            #pragma unroll
            for (int nf = 0; nf < 4; nf++) {
                ldsm_x2(bh[nf], bhiA + (uint32_t)nf * 2176 + kb);
                ldsm_x2(bl[nf], bloA + (uint32_t)nf * 2176 + kb);
            }
            #pragma unroll
            for (int mf = 0; mf < 2; mf++)
                #pragma unroll
                for (int nf = 0; nf < 4; nf++) {
                    mma_bf16(acc[mf][nf], ah[mf], bh[nf]);
                    mma_bf16(acc[mf][nf], ah[mf], bl[nf]);
                    mma_bf16(acc[mf][nf], al[mf], bh[nf]);
                }
        }

        // epilogue: per-warp column sums of v*tanh(T)
        float p[8];
        #pragma unroll
        for (int nf = 0; nf < 4; nf++)
            #pragma unroll
            for (int cc = 0; cc < 2; cc++)
                p[nf * 2 + cc] = vr[0] * tanh_fast(acc[0][nf][cc])
                               + vr[1] * tanh_fast(acc[0][nf][2 + cc])
                               + vr[2] * tanh_fast(acc[1][nf][cc])
                               + vr[3] * tanh_fast(acc[1][nf][2 + cc]);
        #pragma unroll
        for (int st = 4; st <= 16; st <<= 1)
            #pragma unroll
            for (int idx = 0; idx < 8; idx++)
                p[idx] += __shfl_xor_sync(0xffffffffu, p[idx], st);
        if (rq == 0) {
            #pragma unroll
            for (int nf = 0; nf < 4; nf++)
                #pragma unroll
                for (int cc = 0; cc < 2; cc++) {
                    int col = warp_n * 32 + nf * 8 + lane * 2 + cc;
                    red[col * 5 + warp_m] = p[nf * 2 + cc];
                }
        }
        __syncthreads();                               // red ready

        // tile energies + warp maxes (threads 0..127 <-> tile-local n)
        float e_n = 0.0f;
        if (t < 128) {
            e_n = red[t * 5] + red[t * 5 + 1] + red[t * 5 + 2] + red[t * 5 + 3];
            float wm = e_n;
            #pragma unroll
            for (int o = 16; o; o >>= 1) wm = fmaxf(wm, __shfl_xor_sync(0xffffffffu, wm, o));
            if (lane == 0) rscr[wid] = wm;
        }
        __syncthreads();                               // rscr ready

        float m_new = fmaxf(fmaxf(rscr[0], rscr[1]), fmaxf(rscr[2], rscr[3]));
        m_new = fmaxf(m_new, m_run);
        float sscale = __expf(m_run - m_new);          // 0 on first tile
        ctx.x *= sscale; ctx.y *= sscale;
        if (t < 128) {
            float pex = __expf(e_n - m_new);
            Zp = Zp * sscale + pex;
            pw[t] = pex;
        }
        m_run = m_new;
        __syncthreads();                               // pw ready

        // ctx += pw * H  (H = hi + lo from resident tile)
        const char* Bh = sm + OFF_B;
        const char* Bl = sm + OFF_BLO;
        #pragma unroll 4
        for (int i = 0; i < 16; i++) {
            int n = ng * 16 + i;
            uint32_t hw = *(const uint32_t*)(Bh + n * 272 + e2 * 4);
            uint32_t lw = *(const uint32_t*)(Bl + n * 272 + e2 * 4);
            float pv = pw[n];
            float hx = __uint_as_float(hw << 16)         + __uint_as_float(lw << 16);
            float hy = __uint_as_float(hw & 0xFFFF0000u) + __uint_as_float(lw & 0xFFFF0000u);
            ctx.x = fmaf(pv, hx, ctx.x);
            ctx.y = fmaf(pv, hy, ctx.y);
        }
        __syncthreads();                               // tile fully consumed
    }

    // ---------------- finalize: Z, ctx reduction, output ----------------
    if (t < 128) {
        float z = Zp;
        #pragma unroll
        for (int o = 16; o; o >>= 1) z += __shfl_xor_sync(0xffffffffu, z, o);
        if (lane == 0) rscr[wid] = z;
    }
    __syncthreads();
    float invZ = 1.0f / (rscr[0] + rscr[1] + rscr[2] + rscr[3]);

    ((float2*)red)[e2 * 8 + ng] = ctx;
    __syncthreads();
    if (t < 64) {
        float2 c2 = make_float2(0.f, 0.f);
        #pragma unroll
        for (int j = 0; j < 8; j++) {
            float2 v = ((const float2*)red)[t * 8 + j];
            c2.x += v.x; c2.y += v.y;
        }
        out[b * 128 + 2 * t]     = c2.x * invZ;
        out[b * 128 + 2 * t + 1] = c2.y * invZ;
    }
}

extern "C" void kernel_launch(void* const* d_in, const int* in_sizes, int n_in,
                              void* d_out, int out_size)
{
    const int*   seq = (const int*)  d_in[0];
    const float* emb = (const float*)d_in[1];
    const float* cw  = (const float*)d_in[2];
    const float* cb  = (const float*)d_in[3];
    const float* Wa  = (const float*)d_in[4];
    const float* va  = (const float*)d_in[5];
    float* out = (float*)d_out;

    cudaFuncSetAttribute(dingo_mma_kernel,
                         cudaFuncAttributeMaxDynamicSharedMemorySize, SMEM_TOTAL);
    dingo_mma_kernel<<<128, THREADS, SMEM_TOTAL>>>(seq, emb, cw, cb, Wa, va, out);
}

// round 13
// speedup vs baseline: 2.4914x; 1.1024x over previous
#include <cuda_runtime.h>
#include <cstdint>
#include <math.h>

#define THREADS 512

// B=128, L=8194, C=32, PL=8192, S=4, D=128(M=K), N=2048, 16 n-tiles of 128.
// T = W_a @ H per n-tile via mma.sync.m16n8k16 bf16 split-2 (drop lo*lo).
// Online-softmax fusion of pooling (flash style).  THIS ROUND: B tiles are
// double-buffered; conv for tile t+1 is interleaved INSIDE tile t's MMA
// k-loop (writes the other buffer), hiding conv behind tensor-pipe latency.
// Tiles [row][k] bf16, pitch 272B (16 mod 128 -> conflict-free ldmatrix).

#define OFF_AHI   0          // bf16 Whi [128][136]   34,816 B
#define OFF_ALO   34816      // bf16 Wlo              34,816 B
#define OFF_B0H   69632      // buf0 Hhi              34,816 B
#define OFF_B0L   104448     // buf0 Hlo              34,816 B
#define OFF_B1H   139264     // buf1 Hhi              34,816 B
#define OFF_B1L   174080     // buf1 Hlo              34,816 B
#define OFF_AT    208896     // float AT[26][3][32]    9,984 B
#define OFF_RED   218880     // 4,096 B scratch (epi cols / final ctx)
#define OFF_PW    222976     // float[128] tile softmax numerators
#define OFF_VA    223488     // float[128]
#define OFF_BIAS  224000     // float[32]
#define OFF_RSCR  224128     // float[16]
#define OFF_SEQ   224192     // uchar[8208]
#define SMEM_TOTAL 232400    // <= 232,448 (227 KB cap)

__device__ __forceinline__ uint32_t pack_bf(float lo, float hi) {
    uint32_t r;
    asm("cvt.rn.bf16x2.f32 %0, %1, %2;" : "=r"(r) : "f"(hi), "f"(lo));
    return r;
}
__device__ __forceinline__ float tanh_fast(float x) {
    float e2 = __expf(2.0f * x);
    return 1.0f - __fdividef(2.0f, e2 + 1.0f);
}
__device__ __forceinline__ void mma_bf16(float* d, const uint32_t* a, const uint32_t* b) {
    asm("mma.sync.aligned.m16n8k16.row.col.f32.bf16.bf16.f32 "
        "{%0,%1,%2,%3}, {%4,%5,%6,%7}, {%8,%9}, {%0,%1,%2,%3};"
        : "+f"(d[0]), "+f"(d[1]), "+f"(d[2]), "+f"(d[3])
        : "r"(a[0]), "r"(a[1]), "r"(a[2]), "r"(a[3]), "r"(b[0]), "r"(b[1]));
}
__device__ __forceinline__ void ldsm_x4(uint32_t* r, uint32_t addr) {
    asm volatile("ldmatrix.sync.aligned.m8n8.x4.shared.b16 {%0,%1,%2,%3}, [%4];"
        : "=r"(r[0]), "=r"(r[1]), "=r"(r[2]), "=r"(r[3]) : "r"(addr));
}
__device__ __forceinline__ void ldsm_x2(uint32_t* r, uint32_t addr) {
    asm volatile("ldmatrix.sync.aligned.m8n8.x2.shared.b16 {%0,%1}, [%2];"
        : "=r"(r[0]), "=r"(r[1]) : "r"(addr));
}
__device__ __forceinline__ uint32_t smem_u32(const void* p) {
    uint32_t a;
    asm("{ .reg .u64 t; cvta.to.shared.u64 t, %1; cvt.u32.u64 %0, t; }" : "=r"(a) : "l"(p));
    return a;
}

// Conv values for unit u (sct pair sp=u>>5, chunk ch=u&31), channel c=lane.
// Letters warp-uniform; AT[l][k][c] loads lane-coalesced.
__device__ __forceinline__ void conv_vals(const char* sm, int n0, int u, int c,
                                          float bias, float* ya, float* yb) {
    const unsigned char* seqb = (const unsigned char*)(sm + OFF_SEQ);
    const float* AT = (const float*)(sm + OFF_AT);
    int sp = u >> 5, ch = u & 31;
    int na = ch * 4;
    int p0 = sp * 4096 + n0 + na;
    int p1 = p0 + 2048;
    uint32_t wa0 = *(const uint32_t*)(seqb + p0);
    uint32_t wb0 = *(const uint32_t*)(seqb + p0 + 4);
    uint32_t wa1 = *(const uint32_t*)(seqb + p1);
    uint32_t wb1 = *(const uint32_t*)(seqb + p1 + 4);
#define TBL(l, k) AT[(((l) * 3 + (k)) << 5) + c]
    {
        int l0 = wa0 & 255, l1 = (wa0 >> 8) & 255, l2 = (wa0 >> 16) & 255, l3 = wa0 >> 24;
        int l4 = wb0 & 255, l5 = (wb0 >> 8) & 255;
        float t00 = TBL(l0,0), t10 = TBL(l1,0), t11 = TBL(l1,1), t20 = TBL(l2,0);
        float t21 = TBL(l2,1), t22 = TBL(l2,2), t30 = TBL(l3,0), t31 = TBL(l3,1);
        float t32 = TBL(l3,2), t41 = TBL(l4,1), t42 = TBL(l4,2), t52 = TBL(l5,2);
        ya[0] = fmaxf(bias + t00 + t11 + t22, 0.0f);
        ya[1] = fmaxf(bias + t10 + t21 + t32, 0.0f);
        ya[2] = fmaxf(bias + t20 + t31 + t42, 0.0f);
        ya[3] = fmaxf(bias + t30 + t41 + t52, 0.0f);
    }
    {
        int l0 = wa1 & 255, l1 = (wa1 >> 8) & 255, l2 = (wa1 >> 16) & 255, l3 = wa1 >> 24;
        int l4 = wb1 & 255, l5 = (wb1 >> 8) & 255;
        float t00 = TBL(l0,0), t10 = TBL(l1,0), t11 = TBL(l1,1), t20 = TBL(l2,0);
        float t21 = TBL(l2,1), t22 = TBL(l2,2), t30 = TBL(l3,0), t31 = TBL(l3,1);
        float t32 = TBL(l3,2), t41 = TBL(l4,1), t42 = TBL(l4,2), t52 = TBL(l5,2);
        yb[0] = fmaxf(bias + t00 + t11 + t22, 0.0f);
        yb[1] = fmaxf(bias + t10 + t21 + t32, 0.0f);
        yb[2] = fmaxf(bias + t20 + t31 + t42, 0.0f);
        yb[3] = fmaxf(bias + t30 + t41 + t52, 0.0f);
    }
#undef TBL
}

// One conv unit -> bf16 hi/lo rows of buffer bufH (lo at bufH+34816).
__device__ __forceinline__ void conv_unit(char* sm, uint32_t bufH, int n0,
                                          int u, int c, float bias) {
    float ya[4], yb[4];
    conv_vals(sm, n0, u, c, bias, ya, yb);
    int sp = u >> 5, na = (u & 31) * 4;
    int e0 = 4 * c + 2 * sp;
    #pragma unroll
    for (int j = 0; j < 4; j++) {
        int row = na + j;
        uint32_t hw = pack_bf(ya[j], yb[j]);
        float ha = __uint_as_float(hw << 16);
        float hb = __uint_as_float(hw & 0xFFFF0000u);
        uint32_t lw = pack_bf(ya[j] - ha, yb[j] - hb);
        *(uint32_t*)(sm + bufH +         row * 272 + e0 * 2) = hw;
        *(uint32_t*)(sm + bufH + 34816 + row * 272 + e0 * 2) = lw;
    }
}

__global__ void __launch_bounds__(THREADS, 1)
dingo_mma_kernel(const int*   __restrict__ seq,
                 const float* __restrict__ emb,
                 const float* __restrict__ cw,
                 const float* __restrict__ cb,
                 const float* __restrict__ Wa,
                 const float* __restrict__ va,
                 float*       __restrict__ out)
{
    extern __shared__ char sm[];
    const int t    = threadIdx.x;
    const int b    = blockIdx.x;
    const int lane = t & 31;
    const int wid  = t >> 5;
    const uint32_t smb = smem_u32(sm);

    // ---------------- setup ----------------
    const int* seqg = seq + b * 8194;
    unsigned char* seqb = (unsigned char*)(sm + OFF_SEQ);
    for (int i = t; i < 8208; i += THREADS)
        seqb[i] = (i < 8194) ? (unsigned char)seqg[i] : (unsigned char)0;

    for (int i = t; i < 16384; i += THREADS) {      // W_a -> bf16 hi/lo [m][k]
        int d = i >> 7, e = i & 127;
        float w = Wa[i];
        uint32_t hp = pack_bf(w, 0.0f);
        float hf = __uint_as_float(hp << 16);
        uint32_t lp = pack_bf(w - hf, 0.0f);
        *(unsigned short*)(sm + OFF_AHI + d * 272 + e * 2) = (unsigned short)hp;
        *(unsigned short*)(sm + OFF_ALO + d * 272 + e * 2) = (unsigned short)lp;
    }
    {
        float* AT = (float*)(sm + OFF_AT);           // AT[l][k][c]
        for (int i = t; i < 26 * 96; i += THREADS) {
            int l = i / 96, r = i % 96, k = r >> 5, c = r & 31;
            float acc = 0.0f;
            #pragma unroll
            for (int j = 0; j < 5; j++)
                acc += emb[l * 5 + j] * cw[c * 15 + j * 3 + k];
            AT[i] = acc;
        }
    }
    if (t < 128) ((float*)(sm + OFF_VA))[t]   = va[t];
    if (t < 32)  ((float*)(sm + OFF_BIAS))[t] = cb[t];
    __syncthreads();

    const float cbias = ((const float*)(sm + OFF_BIAS))[lane];

    const int warp_m = wid & 3;
    const int warp_n = wid >> 2;
    const uint32_t a_off = (uint32_t)((warp_m * 32 + (lane & 15)) * 272 + (lane >> 4) * 16);
    const uint32_t ahiA  = smb + OFF_AHI + a_off;
    const uint32_t aloA  = smb + OFF_ALO + a_off;
    const int l15 = lane & 15;
    const uint32_t b_off = (uint32_t)((warp_n * 32 + (l15 & 7)) * 272 + (l15 >> 3) * 16);

    const int rq = lane >> 2;
    float vr[4];
    {
        const float* v = (const float*)(sm + OFF_VA);
        vr[0] = v[warp_m * 32 + rq];      vr[1] = v[warp_m * 32 + rq + 8];
        vr[2] = v[warp_m * 32 + rq + 16]; vr[3] = v[warp_m * 32 + rq + 24];
    }
    float* red  = (float*)(sm + OFF_RED);
    float* rscr = (float*)(sm + OFF_RSCR);
    float* pw   = (float*)(sm + OFF_PW);

    // online-softmax state
    const int e2 = t & 63;
    const int ng = t >> 6;
    float  m_run = -INFINITY;
    float  Zp = 0.0f;
    float2 ctx = make_float2(0.0f, 0.0f);

    // prime buf0 with tile 0
    #pragma unroll
    for (int uu = 0; uu < 4; uu++)
        conv_unit(sm, OFF_B0H, 0, wid + uu * 16, lane, cbias);
    __syncthreads();

    // ---------------- fused pipelined pass over 16 tiles ----------------
    for (int tile = 0; tile < 16; tile++) {
        const int cur = tile & 1;
        const uint32_t curH = cur ? OFF_B1H : OFF_B0H;
        const uint32_t nxtH = cur ? OFF_B0H : OFF_B1H;
        const uint32_t bhiA = smb + curH + b_off;
        const uint32_t bloA = bhiA + 34816;
        const bool notlast = (tile < 15);
        const int n0n = (tile + 1) * 128;

        float acc[2][4][4];
        #pragma unroll
        for (int mf = 0; mf < 2; mf++)
            #pragma unroll
            for (int nf = 0; nf < 4; nf++)
                #pragma unroll
                for (int r = 0; r < 4; r++) acc[mf][nf][r] = 0.0f;

        #pragma unroll
        for (int ks = 0; ks < 8; ks++) {
            const uint32_t kb = (uint32_t)ks * 32;
            uint32_t ah[2][4], al[2][4], bh[4][2], bl[4][2];
            ldsm_x4(ah[0], ahiA + kb);
            ldsm_x4(ah[1], ahiA + 4352 + kb);
            ldsm_x4(al[0], aloA + kb);
            ldsm_x4(al[1], aloA + 4352 + kb);
            #pragma unroll
            for (int nf = 0; nf < 4; nf++) {
                ldsm_x2(bh[nf], bhiA + (uint32_t)nf * 2176 + kb);
                ldsm_x2(bl[nf], bloA + (uint32_t)nf * 2176 + kb);
            }
            #pragma unroll
            for (int mf = 0; mf < 2; mf++)
                #pragma unroll
                for (int nf = 0; nf < 4; nf++) {
                    mma_bf16(acc[mf][nf], ah[mf], bh[nf]);
                    mma_bf16(acc[mf][nf], ah[mf], bl[nf]);
                    mma_bf16(acc[mf][nf], al[mf], bh[nf]);
                }
            // interleave one conv unit for the NEXT tile after even k-steps;
            // writes the other buffer -> no barrier needed, hides MMA latency.
            if ((ks & 1) == 0 && notlast)
                conv_unit(sm, nxtH, n0n, wid + (ks >> 1) * 16, lane, cbias);
        }

        // epilogue: per-warp column sums of v*tanh(T)
        float p[8];
        #pragma unroll
        for (int nf = 0; nf < 4; nf++)
            #pragma unroll
            for (int cc = 0; cc < 2; cc++)
                p[nf * 2 + cc] = vr[0] * tanh_fast(acc[0][nf][cc])
                               + vr[1] * tanh_fast(acc[0][nf][2 + cc])
                               + vr[2] * tanh_fast(acc[1][nf][cc])
                               + vr[3] * tanh_fast(acc[1][nf][2 + cc]);
        #pragma unroll
        for (int st = 4; st <= 16; st <<= 1)
            #pragma unroll
            for (int idx = 0; idx < 8; idx++)
                p[idx] += __shfl_xor_sync(0xffffffffu, p[idx], st);
        if (rq == 0) {
            #pragma unroll
            for (int nf = 0; nf < 4; nf++)
                #pragma unroll
                for (int cc = 0; cc < 2; cc++) {
                    int col = warp_n * 32 + nf * 8 + lane * 2 + cc;
                    red[col * 5 + warp_m] = p[nf * 2 + cc];
                }
        }
        __syncthreads();                               // S1: red + next-B ready

        float e_n = 0.0f;
        if (t < 128) {
            e_n = red[t * 5] + red[t * 5 + 1] + red[t * 5 + 2] + red[t * 5 + 3];
            float wm = e_n;
            #pragma unroll
            for (int o = 16; o; o >>= 1) wm = fmaxf(wm, __shfl_xor_sync(0xffffffffu, wm, o));
            if (lane == 0) rscr[wid] = wm;
        }
        __syncthreads();                               // S2: rscr ready

        float m_new = fmaxf(fmaxf(rscr[0], rscr[1]), fmaxf(rscr[2], rscr[3]));
        m_new = fmaxf(m_new, m_run);
        float sscale = __expf(m_run - m_new);          // 0 on first tile
        ctx.x *= sscale; ctx.y *= sscale;
        if (t < 128) {
            float pex = __expf(e_n - m_new);
            Zp = Zp * sscale + pex;
            pw[t] = pex;
        }
        m_run = m_new;
        __syncthreads();                               // S3: pw ready

        // ctx += pw * H  (H = hi + lo from current buffer)
        const char* Bh = sm + curH;
        const char* Bl = Bh + 34816;
        #pragma unroll 4
        for (int i = 0; i < 16; i++) {
            int n = ng * 16 + i;
            uint32_t hw = *(const uint32_t*)(Bh + n * 272 + e2 * 4);
            uint32_t lw = *(const uint32_t*)(Bl + n * 272 + e2 * 4);
            float pv = pw[n];
            float hx = __uint_as_float(hw << 16)         + __uint_as_float(lw << 16);
            float hy = __uint_as_float(hw & 0xFFFF0000u) + __uint_as_float(lw & 0xFFFF0000u);
            ctx.x = fmaf(pv, hx, ctx.x);
            ctx.y = fmaf(pv, hy, ctx.y);
        }
        __syncthreads();                               // S4: buf[cur] reusable
    }

    // ---------------- finalize ----------------
    if (t < 128) {
        float z = Zp;
        #pragma unroll
        for (int o = 16; o; o >>= 1) z += __shfl_xor_sync(0xffffffffu, z, o);
        if (lane == 0) rscr[wid] = z;
    }
    __syncthreads();
    float invZ = 1.0f / (rscr[0] + rscr[1] + rscr[2] + rscr[3]);

    ((float2*)red)[e2 * 8 + ng] = ctx;
    __syncthreads();
    if (t < 64) {
        float2 c2 = make_float2(0.f, 0.f);
        #pragma unroll
        for (int j = 0; j < 8; j++) {
            float2 v = ((const float2*)red)[t * 8 + j];
            c2.x += v.x; c2.y += v.y;
        }
        out[b * 128 + 2 * t]     = c2.x * invZ;
        out[b * 128 + 2 * t + 1] = c2.y * invZ;
    }
}

extern "C" void kernel_launch(void* const* d_in, const int* in_sizes, int n_in,
                              void* d_out, int out_size)
{
    const int*   seq = (const int*)  d_in[0];
    const float* emb = (const float*)d_in[1];
    const float* cw  = (const float*)d_in[2];
    const float* cb  = (const float*)d_in[3];
    const float* Wa  = (const float*)d_in[4];
    const float* va  = (const float*)d_in[5];
    float* out = (float*)d_out;

    cudaFuncSetAttribute(dingo_mma_kernel,
                         cudaFuncAttributeMaxDynamicSharedMemorySize, SMEM_TOTAL);
    dingo_mma_kernel<<<128, THREADS, SMEM_TOTAL>>>(seq, emb, cw, cb, Wa, va, out);
}

// round 16
// speedup vs baseline: 2.6255x; 1.0538x over previous
#include <cuda_runtime.h>
#include <cstdint>
#include <math.h>

#define THREADS 640   // 16 consumer warps (MMA) + 4 producer warps (conv/softmax/ctx)

// B=128, L=8194, C=32, PL=8192, S=4, D=128(M=K), N=2048, 16 n-tiles of 128.
// T = W_a @ H per n-tile via mma.sync.m16n8k16 bf16 split-2 (drop lo*lo).
// Online-softmax pooling.  Warp-specialized: consumers run a conv-free
// MMA+tanh+red pipeline; one producer warp per SMSP runs conv(t+1),
// softmax(t-1), ctx(t-1) concurrently.  1 block barrier per tile.
// BARRIER DISCIPLINE: every thread arrives at barrier 0 exactly 18 times
// (setup + prime + 16 tiles) — consumers have an explicit prime-wait sync.
// Producer-internal ordering uses named barrier 1 (128 threads).

#define OFF_AHI   0          // bf16 Whi [128][136]   34,816 B
#define OFF_ALO   34816      // bf16 Wlo              34,816 B
#define OFF_B0H   69632      // buf0 Hhi              34,816 B
#define OFF_B0L   104448     // buf0 Hlo              34,816 B
#define OFF_B1H   139264     // buf1 Hhi              34,816 B
#define OFF_B1L   174080     // buf1 Hlo              34,816 B
#define OFF_AT    208896     // float AT[26][3][32]    9,984 B
#define OFF_RED0  218880     // float[512] epi cols, tile even   2,048 B
#define OFF_RED1  220928     // float[512] epi cols, tile odd    2,048 B
#define OFF_PW    222976     // float[128]              512 B
#define OFF_BIAS  223488     // float[32]               128 B
#define OFF_RSCR  223616     // float[16]                64 B
#define OFF_SEQ   223680     // uchar[8208]
#define SMEM_TOTAL 231888    // <= 232,448

__device__ __forceinline__ uint32_t pack_bf(float lo, float hi) {
    uint32_t r;
    asm("cvt.rn.bf16x2.f32 %0, %1, %2;" : "=r"(r) : "f"(hi), "f"(lo));
    return r;
}
__device__ __forceinline__ float tanh_fast(float x) {
    float e2 = __expf(2.0f * x);
    return 1.0f - __fdividef(2.0f, e2 + 1.0f);
}
__device__ __forceinline__ void mma_bf16(float* d, const uint32_t* a, const uint32_t* b) {
    asm("mma.sync.aligned.m16n8k16.row.col.f32.bf16.bf16.f32 "
        "{%0,%1,%2,%3}, {%4,%5,%6,%7}, {%8,%9}, {%0,%1,%2,%3};"
        : "+f"(d[0]), "+f"(d[1]), "+f"(d[2]), "+f"(d[3])
        : "r"(a[0]), "r"(a[1]), "r"(a[2]), "r"(a[3]), "r"(b[0]), "r"(b[1]));
}
__device__ __forceinline__ void ldsm_x4(uint32_t* r, uint32_t addr) {
    asm volatile("ldmatrix.sync.aligned.m8n8.x4.shared.b16 {%0,%1,%2,%3}, [%4];"
        : "=r"(r[0]), "=r"(r[1]), "=r"(r[2]), "=r"(r[3]) : "r"(addr));
}
__device__ __forceinline__ void ldsm_x2(uint32_t* r, uint32_t addr) {
    asm volatile("ldmatrix.sync.aligned.m8n8.x2.shared.b16 {%0,%1}, [%2];"
        : "=r"(r[0]), "=r"(r[1]) : "r"(addr));
}
__device__ __forceinline__ uint32_t smem_u32(const void* p) {
    uint32_t a;
    asm("{ .reg .u64 t; cvta.to.shared.u64 t, %1; cvt.u32.u64 %0, t; }" : "=r"(a) : "l"(p));
    return a;
}
#define PBAR() asm volatile("bar.sync 1, 128;" ::: "memory")

// Conv values for unit u (sct pair sp=u>>5, chunk ch=u&31), channel c=lane.
__device__ __forceinline__ void conv_vals(const char* sm, int n0, int u, int c,
                                          float bias, float* ya, float* yb) {
    const unsigned char* seqb = (const unsigned char*)(sm + OFF_SEQ);
    const float* AT = (const float*)(sm + OFF_AT);
    int sp = u >> 5, ch = u & 31;
    int na = ch * 4;
    int p0 = sp * 4096 + n0 + na;
    int p1 = p0 + 2048;
    uint32_t wa0 = *(const uint32_t*)(seqb + p0);
    uint32_t wb0 = *(const uint32_t*)(seqb + p0 + 4);
    uint32_t wa1 = *(const uint32_t*)(seqb + p1);
    uint32_t wb1 = *(const uint32_t*)(seqb + p1 + 4);
#define TBL(l, k) AT[(((l) * 3 + (k)) << 5) + c]
    {
        int l0 = wa0 & 255, l1 = (wa0 >> 8) & 255, l2 = (wa0 >> 16) & 255, l3 = wa0 >> 24;
        int l4 = wb0 & 255, l5 = (wb0 >> 8) & 255;
        float t00 = TBL(l0,0), t10 = TBL(l1,0), t11 = TBL(l1,1), t20 = TBL(l2,0);
        float t21 = TBL(l2,1), t22 = TBL(l2,2), t30 = TBL(l3,0), t31 = TBL(l3,1);
        float t32 = TBL(l3,2), t41 = TBL(l4,1), t42 = TBL(l4,2), t52 = TBL(l5,2);
        ya[0] = fmaxf(bias + t00 + t11 + t22, 0.0f);
        ya[1] = fmaxf(bias + t10 + t21 + t32, 0.0f);
        ya[2] = fmaxf(bias + t20 + t31 + t42, 0.0f);
        ya[3] = fmaxf(bias + t30 + t41 + t52, 0.0f);
    }
    {
        int l0 = wa1 & 255, l1 = (wa1 >> 8) & 255, l2 = (wa1 >> 16) & 255, l3 = wa1 >> 24;
        int l4 = wb1 & 255, l5 = (wb1 >> 8) & 255;
        float t00 = TBL(l0,0), t10 = TBL(l1,0), t11 = TBL(l1,1), t20 = TBL(l2,0);
        float t21 = TBL(l2,1), t22 = TBL(l2,2), t30 = TBL(l3,0), t31 = TBL(l3,1);
        float t32 = TBL(l3,2), t41 = TBL(l4,1), t42 = TBL(l4,2), t52 = TBL(l5,2);
        yb[0] = fmaxf(bias + t00 + t11 + t22, 0.0f);
        yb[1] = fmaxf(bias + t10 + t21 + t32, 0.0f);
        yb[2] = fmaxf(bias + t20 + t31 + t42, 0.0f);
        yb[3] = fmaxf(bias + t30 + t41 + t52, 0.0f);
    }
#undef TBL
}

__device__ __forceinline__ void conv_unit(char* sm, uint32_t bufH, int n0,
                                          int u, int c, float bias) {
    float ya[4], yb[4];
    conv_vals(sm, n0, u, c, bias, ya, yb);
    int sp = u >> 5, na = (u & 31) * 4;
    int e0 = 4 * c + 2 * sp;
    #pragma unroll
    for (int j = 0; j < 4; j++) {
        int row = na + j;
        uint32_t hw = pack_bf(ya[j], yb[j]);
        float ha = __uint_as_float(hw << 16);
        float hb = __uint_as_float(hw & 0xFFFF0000u);
        uint32_t lw = pack_bf(ya[j] - ha, yb[j] - hb);
        *(uint32_t*)(sm + bufH +         row * 272 + e0 * 2) = hw;
        *(uint32_t*)(sm + bufH + 34816 + row * 272 + e0 * 2) = lw;
    }
}

// Producer stage for tile tprev: energies from red[tprev&1], online-softmax
// update, ctx accumulate from buf[tprev&1].  Ends with PBAR (buffer handoff).
__device__ __forceinline__ void prod_softmax_ctx(char* sm, int tprev, int pt,
                                                 int lane, int wid2,
                                                 float& m_run, float& Zp, float2& ctx) {
    float* rscr = (float*)(sm + OFF_RSCR);
    float* pw   = (float*)(sm + OFF_PW);
    const float* redr = (const float*)(sm + ((tprev & 1) ? OFF_RED1 : OFF_RED0));
    float4 r4 = *(const float4*)(redr + pt * 4);
    float e_n = (r4.x + r4.y) + (r4.z + r4.w);
    float wm = e_n;
    #pragma unroll
    for (int o = 16; o; o >>= 1) wm = fmaxf(wm, __shfl_xor_sync(0xffffffffu, wm, o));
    if (lane == 0) rscr[wid2] = wm;
    PBAR();
    float m_new = fmaxf(fmaxf(fmaxf(rscr[0], rscr[1]), fmaxf(rscr[2], rscr[3])), m_run);
    float ss = __expf(m_run - m_new);          // 0 on first tile
    ctx.x *= ss; ctx.y *= ss;
    float pex = __expf(e_n - m_new);
    Zp = Zp * ss + pex;
    pw[pt] = pex;
    m_run = m_new;
    PBAR();                                     // pw ready
    const char* Bh = sm + ((tprev & 1) ? OFF_B1H : OFF_B0H);
    const char* Bl = Bh + 34816;
    const int e2 = pt & 63;
    const int nb = (pt >> 6) * 64;
    #pragma unroll 4
    for (int i = 0; i < 64; i++) {
        int n = nb + i;
        uint32_t hw = *(const uint32_t*)(Bh + n * 272 + e2 * 4);
        uint32_t lw = *(const uint32_t*)(Bl + n * 272 + e2 * 4);
        float pv = pw[n];
        ctx.x = fmaf(pv, __uint_as_float(hw << 16)         + __uint_as_float(lw << 16),        ctx.x);
        ctx.y = fmaf(pv, __uint_as_float(hw & 0xFFFF0000u) + __uint_as_float(lw & 0xFFFF0000u), ctx.y);
    }
    PBAR();                                     // buf[tprev&1] free for conv
}

__global__ void __launch_bounds__(THREADS, 1)
dingo_ws_kernel(const int*   __restrict__ seq,
                const float* __restrict__ emb,
                const float* __restrict__ cw,
                const float* __restrict__ cb,
                const float* __restrict__ Wa,
                const float* __restrict__ va,
                float*       __restrict__ out)
{
    extern __shared__ char sm[];
    const int t    = threadIdx.x;
    const int b    = blockIdx.x;
    const int lane = t & 31;
    const int wid  = t >> 5;              // 0..19
    const uint32_t smb = smem_u32(sm);

    // ---------------- setup (all 640 threads) ----------------
    const int* seqg = seq + b * 8194;
    unsigned char* seqb = (unsigned char*)(sm + OFF_SEQ);
    for (int i = t; i < 8208; i += THREADS)
        seqb[i] = (i < 8194) ? (unsigned char)seqg[i] : (unsigned char)0;

    for (int i = t; i < 16384; i += THREADS) {      // W_a -> bf16 hi/lo [m][k]
        int d = i >> 7, e = i & 127;
        float w = Wa[i];
        uint32_t hp = pack_bf(w, 0.0f);
        float hf = __uint_as_float(hp << 16);
        uint32_t lp = pack_bf(w - hf, 0.0f);
        *(unsigned short*)(sm + OFF_AHI + d * 272 + e * 2) = (unsigned short)hp;
        *(unsigned short*)(sm + OFF_ALO + d * 272 + e * 2) = (unsigned short)lp;
    }
    {
        float* AT = (float*)(sm + OFF_AT);           // AT[l][k][c]
        for (int i = t; i < 26 * 96; i += THREADS) {
            int l = i / 96, r = i % 96, k = r >> 5, c = r & 31;
            float acc = 0.0f;
            #pragma unroll
            for (int j = 0; j < 5; j++)
                acc += emb[l * 5 + j] * cw[c * 15 + j * 3 + k];
            AT[i] = acc;
        }
    }
    if (t < 32) ((float*)(sm + OFF_BIAS))[t] = cb[t];
    __syncthreads();                                 // B0: setup done

    if (wid < 16) {
        // ================= CONSUMERS: MMA + tanh + red =================
        const int warp_m = wid & 3;
        const int warp_n = wid >> 2;
        const uint32_t a_off = (uint32_t)((warp_m * 32 + (lane & 15)) * 272 + (lane >> 4) * 16);
        const uint32_t ahiA  = smb + OFF_AHI + a_off;
        const uint32_t aloA  = smb + OFF_ALO + a_off;
        const int l15 = lane & 15;
        const uint32_t b_off = (uint32_t)((warp_n * 32 + (l15 & 7)) * 272 + (l15 >> 3) * 16);
        const int rq = lane >> 2;
        float vr[4];
        vr[0] = va[warp_m * 32 + rq];      vr[1] = va[warp_m * 32 + rq + 8];
        vr[2] = va[warp_m * 32 + rq + 16]; vr[3] = va[warp_m * 32 + rq + 24];

        __syncthreads();                     // B1: wait for buf0 priming
                                             // (pairs with producers' prime sync)

        for (int tile = 0; tile < 16; tile++) {
            const uint32_t bhiA = smb + ((tile & 1) ? OFF_B1H : OFF_B0H) + b_off;
            const uint32_t bloA = bhiA + 34816;

            float acc[2][4][4];
            #pragma unroll
            for (int mf = 0; mf < 2; mf++)
                #pragma unroll
                for (int nf = 0; nf < 4; nf++)
                    #pragma unroll
                    for (int r = 0; r < 4; r++) acc[mf][nf][r] = 0.0f;

            #pragma unroll
            for (int ks = 0; ks < 8; ks++) {
                const uint32_t kb = (uint32_t)ks * 32;
                uint32_t ah[2][4], al[2][4], bh[4][2], bl[4][2];
                ldsm_x4(ah[0], ahiA + kb);
                ldsm_x4(ah[1], ahiA + 4352 + kb);
                ldsm_x4(al[0], aloA + kb);
                ldsm_x4(al[1], aloA + 4352 + kb);
                #pragma unroll
                for (int nf = 0; nf < 4; nf++) {
                    ldsm_x2(bh[nf], bhiA + (uint32_t)nf * 2176 + kb);
                    ldsm_x2(bl[nf], bloA + (uint32_t)nf * 2176 + kb);
                }
                #pragma unroll
                for (int mf = 0; mf < 2; mf++)
                    #pragma unroll
                    for (int nf = 0; nf < 4; nf++) {
                        mma_bf16(acc[mf][nf], ah[mf], bh[nf]);
                        mma_bf16(acc[mf][nf], ah[mf], bl[nf]);
                        mma_bf16(acc[mf][nf], al[mf], bh[nf]);
                    }
            }

            float p[8];
            #pragma unroll
            for (int nf = 0; nf < 4; nf++)
                #pragma unroll
                for (int cc = 0; cc < 2; cc++)
                    p[nf * 2 + cc] = vr[0] * tanh_fast(acc[0][nf][cc])
                                   + vr[1] * tanh_fast(acc[0][nf][2 + cc])
                                   + vr[2] * tanh_fast(acc[1][nf][cc])
                                   + vr[3] * tanh_fast(acc[1][nf][2 + cc]);
            #pragma unroll
            for (int st = 4; st <= 16; st <<= 1)
                #pragma unroll
                for (int idx = 0; idx < 8; idx++)
                    p[idx] += __shfl_xor_sync(0xffffffffu, p[idx], st);
            if (rq == 0) {
                float* redw = (float*)(sm + ((tile & 1) ? OFF_RED1 : OFF_RED0));
                #pragma unroll
                for (int nf = 0; nf < 4; nf++)
                    #pragma unroll
                    for (int cc = 0; cc < 2; cc++) {
                        int col = warp_n * 32 + nf * 8 + lane * 2 + cc;
                        redw[(col << 2) + warp_m] = p[nf * 2 + cc];
                    }
            }
            __syncthreads();                 // R_tile
        }
        // consumers done: 18 barrier-0 arrivals total, then exit.
    } else {
        // ================= PRODUCERS: conv + softmax + ctx =================
        const int pt   = t - 512;                // 0..127
        const int wid2 = wid - 16;               // 0..3
        const float cbias = ((const float*)(sm + OFF_BIAS))[lane];
        float  m_run = -INFINITY;
        float  Zp = 0.0f;
        float2 ctx = make_float2(0.0f, 0.0f);

        // prime buf0 with tile 0
        #pragma unroll
        for (int uu = 0; uu < 16; uu++)
            conv_unit(sm, OFF_B0H, 0, wid2 + uu * 4, lane, cbias);
        __syncthreads();                         // B1: buf0 primed

        for (int tile = 0; tile < 16; tile++) {
            if (tile > 0)
                prod_softmax_ctx(sm, tile - 1, pt, lane, wid2, m_run, Zp, ctx);
            if (tile < 15) {
                const uint32_t nxtH = ((tile + 1) & 1) ? OFF_B1H : OFF_B0H;
                const int n0n = (tile + 1) * 128;
                #pragma unroll
                for (int uu = 0; uu < 16; uu++)
                    conv_unit(sm, nxtH, n0n, wid2 + uu * 4, lane, cbias);
            }
            __syncthreads();                     // R_tile
        }
        // final tile's softmax/ctx (consumers exited; named bars only)
        prod_softmax_ctx(sm, 15, pt, lane, wid2, m_run, Zp, ctx);

        // Z reduction
        float* rscr = (float*)(sm + OFF_RSCR);
        float z = Zp;
        #pragma unroll
        for (int o = 16; o; o >>= 1) z += __shfl_xor_sync(0xffffffffu, z, o);
        if (lane == 0) rscr[wid2] = z;
        PBAR();
        float invZ = 1.0f / (rscr[0] + rscr[1] + rscr[2] + rscr[3]);

        ((float2*)(sm + OFF_RED0))[pt] = ctx;    // slot pt = half*64 + e2
        PBAR();
        if (pt < 64) {
            float2 a = ((const float2*)(sm + OFF_RED0))[pt];
            float2 c = ((const float2*)(sm + OFF_RED0))[64 + pt];
            out[b * 128 + 2 * pt]     = (a.x + c.x) * invZ;
            out[b * 128 + 2 * pt + 1] = (a.y + c.y) * invZ;
        }
    }
}

extern "C" void kernel_launch(void* const* d_in, const int* in_sizes, int n_in,
                              void* d_out, int out_size)
{
    const int*   seq = (const int*)  d_in[0];
    const float* emb = (const float*)d_in[1];
    const float* cw  = (const float*)d_in[2];
    const float* cb  = (const float*)d_in[3];
    const float* Wa  = (const float*)d_in[4];
    const float* va  = (const float*)d_in[5];
    float* out = (float*)d_out;

    cudaFuncSetAttribute(dingo_ws_kernel,
                         cudaFuncAttributeMaxDynamicSharedMemorySize, SMEM_TOTAL);
    dingo_ws_kernel<<<128, THREADS, SMEM_TOTAL>>>(seq, emb, cw, cb, Wa, va, out);
}